// round 14
// baseline (speedup 1.0000x reference)
#include <cuda_runtime.h>

// ---------------------------------------------------------------------------
// WT_series_decomp: 4-level lowpass DWT analysis+synthesis, season = x - trend.
// R7 base (2 CTAs/row, 512 thr, 49.7KB smem, 4 CTAs/SM) with t2+t3+final
// FUSED into one span: each thread makes 16 outputs from t1 via register
// recompute (t2win[9], t3win[11]). Barrier spans 8 -> 6.
// ---------------------------------------------------------------------------

#define NT      512
#define N0      32768
#define NROWS   512
#define HALF    16777216

#define P1_ALLOC 8264
#define P2_ALLOC 4140
#define SMEM_FLOATS (8 + P1_ALLOC + 8 + P2_ALLOC)   // 12420
#define SMEM_BYTES  (SMEM_FLOATS * 4)               // 49680 -> 4 CTAs/SM

// DEC_LO
#define G0 (-0.010597401784997278f)
#define G1 ( 0.032883011666982945f)
#define G2 ( 0.030841381835986965f)
#define G3 (-0.18703481171888114f)
#define G4 (-0.02798376941698385f)
#define G5 ( 0.6308807679295904f)
#define G6 ( 0.7148465705525415f)
#define G7 ( 0.23037781330885523f)
// H[k] = DEC_LO[7-k]
#define H0 G7
#define H1 G6
#define H2 G5
#define H3 G4
#define H4 G3
#define H5 G2
#define H6 G1
#define H7 G0

// upsample taps: even output uses {G1,G3,G5,G7}, odd uses {G0,G2,G4,G6}
#define UPE(a,b,c,d) fmaf((a), G1, fmaf((b), G3, fmaf((c), G5, (d) * G7)))
#define UPO(a,b,c,d) fmaf((a), G0, fmaf((b), G2, fmaf((c), G4, (d) * G6)))

__device__ __forceinline__ float dot8(float2 a, float2 b, float2 c, float2 d) {
    float s = a.x * H0;
    s = fmaf(a.y, H1, s);
    s = fmaf(b.x, H2, s);
    s = fmaf(b.y, H3, s);
    s = fmaf(c.x, H4, s);
    s = fmaf(c.y, H5, s);
    s = fmaf(d.x, H6, s);
    s = fmaf(d.y, H7, s);
    return s;
}

// Level-1 analysis from GLOBAL x (pairwise). Fast for p in [p_lo, p_hi).
__device__ __forceinline__ void afb_global(const float* __restrict__ x,
                                           float* __restrict__ out,
                                           int pairs, int n_valid, int o_gbase,
                                           int p_lo, int p_hi, int tid) {
    for (int p = tid; p < pairs; p += NT) {
        int xb = 2 * (o_gbase + 2 * p) - 6;
        float2 a, b, c, d, e;
        if (p >= p_lo && p < p_hi) {
            const float2* pp = (const float2*)(x + xb);
            a = pp[0]; b = pp[1]; c = pp[2]; d = pp[3]; e = pp[4];
        } else {
            float v[10];
#pragma unroll
            for (int k = 0; k < 10; ++k) {
                int ix = xb + k;
                v[k] = (ix >= 0 && ix < N0) ? x[ix] : 0.0f;
            }
            a = make_float2(v[0], v[1]); b = make_float2(v[2], v[3]);
            c = make_float2(v[4], v[5]); d = make_float2(v[6], v[7]);
            e = make_float2(v[8], v[9]);
        }
        float s0 = dot8(a, b, c, d);
        float s1 = dot8(b, c, d, e);
        int o = 2 * p;
        if (o + 1 < n_valid) *(float2*)(out + o) = make_float2(s0, s1);
        else                 out[o] = s0;
    }
}

// Analysis from smem. Pair p reads in[in_off + 4p .. +9] (in_off even).
__device__ __forceinline__ void afb_smem(const float* __restrict__ in,
                                         float* __restrict__ out,
                                         int pairs, int n_valid, int in_off,
                                         int tid) {
    for (int p = tid; p < pairs; p += NT) {
        const float2* pp = (const float2*)(in + in_off + 4 * p);
        float2 a = pp[0], b = pp[1], c = pp[2], d = pp[3], e = pp[4];
        float s0 = dot8(a, b, c, d);
        float s1 = dot8(b, c, d, e);
        int o = 2 * p;
        if (o + 1 < n_valid) *(float2*)(out + o) = make_float2(s0, s1);
        else                 out[o] = s0;
    }
}

// Synthesis quad: local outputs 4q..4q+3, reads in[soff + 2q .. +4].
__device__ __forceinline__ void sfb_smem(const float* __restrict__ in,
                                         float* __restrict__ out,
                                         int quads, int soff, int tid) {
    for (int q = tid; q < quads; q += NT) {
        const float2* pp = (const float2*)(in + soff + 2 * q);
        float2 u = pp[0], v = pp[1];
        float  w = pp[2].x;
        float4 t;
        t.x = UPE(u.x, u.y, v.x, v.y);
        t.y = UPO(u.x, u.y, v.x, v.y);
        t.z = UPE(u.y, v.x, v.y, w);
        t.w = UPO(u.y, v.x, v.y, w);
        *(float4*)(out + 4 * q) = t;
    }
}

__global__ void __launch_bounds__(NT, 4)
wt_kernel(const float* __restrict__ x, float* __restrict__ out) {
    extern __shared__ float sm[];
    float* P1 = sm + 8;
    float* P2 = sm + 8 + P1_ALLOC + 8;

    const int tid = threadIdx.x;
    const int row = blockIdx.x >> 1;
    const int h   = blockIdx.x & 1;
    const float* xr = x + (size_t)row * N0;

    if (tid < 8) { P1[tid - 8] = 0.0f; P2[tid - 8] = 0.0f; }

    if (h == 0) {
        // ---- left half
        afb_global(xr, P1, 4128, 8256, 0, 2, 4128, tid);
        __syncthreads();
        afb_smem(P1, P2, 2064, 4128, -6, tid); __syncthreads();    // lo2
        afb_smem(P2, P1, 1032, 2064, -6, tid); __syncthreads();    // lo3
        afb_smem(P1, P2,  516, 1032, -6, tid); __syncthreads();    // lo4
        sfb_smem(P2, P1,  514, 0, tid); __syncthreads();           // t1
    } else {
        // ---- right half
        afb_global(xr, P1, 4127, 8253, 8134, 0, 4125, tid);        // lo1
        if (tid < 11) P1[8253 + tid] = 0.0f;
        __syncthreads();
        afb_smem(P1, P2, 2064, 4127, 0, tid);                      // lo2
        if (tid < 9) P2[4127 + tid] = 0.0f;
        __syncthreads();
        afb_smem(P2, P1, 1032, 2064, 0, tid);                      // lo3
        if (tid < 8) P1[2064 + tid] = 0.0f;
        __syncthreads();
        afb_smem(P1, P2,  516, 1032, 0, tid); __syncthreads();     // lo4
        sfb_smem(P2, P1,  515, 0, tid); __syncthreads();           // t1
    }

    // ---- fused t2 + t3 + final: 16 outputs per thread-block v from t1.
    // t1 window = t1[base .. base+7], base = 2v (left) / 2v+4 (right).
    const int goff = h << 14;
    const int tb   = h ? 4 : 0;
    const float* t1 = P1;
    float* season = out + (size_t)row * N0 + goff;
    float* trend  = out + (size_t)HALF + (size_t)row * N0 + goff;
    const float4* x4 = (const float4*)(xr + goff);
    float4* s4p = (float4*)season;
    float4* t4p = (float4*)trend;

    for (int v = tid; v < 1024; v += NT) {
        const float2* tp = (const float2*)(t1 + 2 * v + tb);
        float2 A = tp[0], B = tp[1], C = tp[2], D = tp[3];
        float w0 = A.x, w1 = A.y, w2 = B.x, w3 = B.y;
        float w4 = C.x, w5 = C.y, w6 = D.x, w7 = D.y;

        // t2win[0..8]
        float t20 = UPE(w0, w1, w2, w3), t21 = UPO(w0, w1, w2, w3);
        float t22 = UPE(w1, w2, w3, w4), t23 = UPO(w1, w2, w3, w4);
        float t24 = UPE(w2, w3, w4, w5), t25 = UPO(w2, w3, w4, w5);
        float t26 = UPE(w3, w4, w5, w6), t27 = UPO(w3, w4, w5, w6);
        float t28 = UPE(w4, w5, w6, w7);

        // t3win[0..10]
        float u0  = UPE(t20, t21, t22, t23), u1 = UPO(t20, t21, t22, t23);
        float u2  = UPE(t21, t22, t23, t24), u3 = UPO(t21, t22, t23, t24);
        float u4  = UPE(t22, t23, t24, t25), u5 = UPO(t22, t23, t24, t25);
        float u6  = UPE(t23, t24, t25, t26), u7 = UPO(t23, t24, t25, t26);
        float u8  = UPE(t24, t25, t26, t27), u9 = UPO(t24, t25, t26, t27);
        float u10 = UPE(t25, t26, t27, t28);

        // outputs 16v .. 16v+15
        float4 o0, o1, o2, o3;
        o0.x = UPE(u0, u1, u2, u3);  o0.y = UPO(u0, u1, u2, u3);
        o0.z = UPE(u1, u2, u3, u4);  o0.w = UPO(u1, u2, u3, u4);
        o1.x = UPE(u2, u3, u4, u5);  o1.y = UPO(u2, u3, u4, u5);
        o1.z = UPE(u3, u4, u5, u6);  o1.w = UPO(u3, u4, u5, u6);
        o2.x = UPE(u4, u5, u6, u7);  o2.y = UPO(u4, u5, u6, u7);
        o2.z = UPE(u5, u6, u7, u8);  o2.w = UPO(u5, u6, u7, u8);
        o3.x = UPE(u6, u7, u8, u9);  o3.y = UPO(u6, u7, u8, u9);
        o3.z = UPE(u7, u8, u9, u10); o3.w = UPO(u7, u8, u9, u10);

        int bi = 4 * v;
        float4 xa = x4[bi], xb = x4[bi + 1], xc = x4[bi + 2], xd = x4[bi + 3];
        t4p[bi]     = o0;
        t4p[bi + 1] = o1;
        t4p[bi + 2] = o2;
        t4p[bi + 3] = o3;
        s4p[bi]     = make_float4(xa.x - o0.x, xa.y - o0.y, xa.z - o0.z, xa.w - o0.w);
        s4p[bi + 1] = make_float4(xb.x - o1.x, xb.y - o1.y, xb.z - o1.z, xb.w - o1.w);
        s4p[bi + 2] = make_float4(xc.x - o2.x, xc.y - o2.y, xc.z - o2.z, xc.w - o2.w);
        s4p[bi + 3] = make_float4(xd.x - o3.x, xd.y - o3.y, xd.z - o3.z, xd.w - o3.w);
    }
}

extern "C" void kernel_launch(void* const* d_in, const int* in_sizes, int n_in,
                              void* d_out, int out_size) {
    const float* x = (const float*)d_in[0];
    float* out = (float*)d_out;
    cudaFuncSetAttribute(wt_kernel, cudaFuncAttributeMaxDynamicSharedMemorySize,
                         SMEM_BYTES);
    wt_kernel<<<2 * NROWS, NT, SMEM_BYTES>>>(x, out);
}